// round 6
// baseline (speedup 1.0000x reference)
#include <cuda_runtime.h>
#include <cuda_bf16.h>
#include <cstdint>

#define Bb   256
#define Dd   256
#define Vv   2000
#define VTt  10000
#define OPTo 16
#define SEQs 10
#define SRCs 40
#define G3   768
#define GSTEP 64
#define RPB   4

#define OFF_OPT  164352
#define OFF_TOPO 168448
#define OFF_EX   178688

// ---------------- device scratch ----------------
__device__ float d_ts[Bb*Dd];
__device__ float d_clog[SEQs*Bb*Vv];
__device__ unsigned char d_w[SEQs*Bb*Vv];
__device__ int   d_sym[Bb*SEQs];
__device__ __nv_bfloat16 d_Ahi[Bb*SEQs*2*Dd];
__device__ __nv_bfloat16 d_WhiT[(size_t)VTt*2*Dd];

__device__ __forceinline__ unsigned f2mono(float f) {
    unsigned u = __float_as_uint(f);
    return (u & 0x80000000u) ? ~u : (u | 0x80000000u);
}

// ---------------- grammar w masks ----------------
__global__ void k_w(const int* __restrict__ gg) {
    int tb = blockIdx.x;            // t*B + b
    int t = tb / Bb, b = tb % Bb;
    int tid = threadIdx.x;          // 64 threads
    __shared__ unsigned char ws[Vv];
    __shared__ int f0;
    for (int v = tid; v < Vv; v += 64) ws[v] = 0;
    if (tid == 0) f0 = 0;
    __syncthreads();
    if (tid < OPTo) {
        int base = ((b*OPTo + tid)*4)*SEQs + t;
        int sym = gg[base];
        int m   = gg[base + 3*SEQs];
        if (m) { if (sym > 0) ws[sym] = 1; else f0 = 1; }
    }
    __syncthreads();
    if (tid == 0) ws[0] = (unsigned char)f0;
    __syncthreads();
    unsigned char* outp = d_w + (size_t)tb*Vv;
    for (int v = tid; v < Vv; v += 64) outp[v] = ws[v];
}

// ---------------- copy small outputs ----------------
__global__ void k_copy(const int* __restrict__ lhs, const int* __restrict__ lmask,
                       const int* __restrict__ gg, float* __restrict__ out) {
    for (int i = blockIdx.x*blockDim.x + threadIdx.x; i < OFF_OPT; i += gridDim.x*blockDim.x) {
        if (i < 256)       out[i] = (float)lhs[i];
        else if (i < 512)  out[i] = (float)lmask[i-256];
        else               out[i] = (float)gg[i-512];
    }
}

// ---------------- prep W: Wtok transpose to (VT,512) bf16 ----------------
__global__ void k_prepW(const float* __restrict__ Wtok) {
    __shared__ float tile[32][33];
    int bi = blockIdx.x;
    int tid = threadIdx.x;
    int tx = tid & 31, ty = tid >> 5;   // 32 x 8
    int n0 = (bi % 313)*32, k0 = (bi / 313)*32;
    #pragma unroll
    for (int i=0;i<4;i++) {
        int k = k0 + ty + i*8, n = n0 + tx;
        tile[ty+i*8][tx] = (n < VTt) ? Wtok[(size_t)k*VTt + n] : 0.f;
    }
    __syncthreads();
    #pragma unroll
    for (int i=0;i<4;i++) {
        int n = n0 + ty + i*8, k = k0 + tx;
        if (n < VTt)
            d_WhiT[(size_t)n*512 + k] = __float2bfloat16(tile[tx][ty+i*8]);
    }
}

// ============================================================================
// k_steps: 64 blocks x 4 batches, all 10 steps local. Pure fp32. No grid sync.
// ============================================================================
// dyn smem layout (floats)
#define SM_MEM   0            // 4*40*256 = 40960
#define SM_GH    40960        // 4*768   = 3072
#define SM_TS0   44032        // 1024
#define SM_TS    45056        // 1024
#define SM_X     46080        // 1024
#define SM_GX    47104        // 3072
#define SM_CAT   50176        // 2048  [r][512] = [ctx|h]
#define SM_SOA   52224        // 1024
#define SM_ATT   53248        // 160
#define SM_TOT_F 53408
#define SM_BYTES (SM_TOT_F*4)

__global__ __launch_bounds__(256) void k_steps(
    const int* __restrict__ lhs, const float* __restrict__ ts0,
    const float* __restrict__ emb, const float* __restrict__ mem,
    const float* __restrict__ Wx, const float* __restrict__ bx,
    const float* __restrict__ Wh, const float* __restrict__ bh,
    const float* __restrict__ Wc, const float* __restrict__ bc,
    const float* __restrict__ Wsym, const float* __restrict__ bsym)
{
    extern __shared__ float sm[];
    float* sMem = sm + SM_MEM;
    float* sGh  = sm + SM_GH;
    float* sTs0 = sm + SM_TS0;
    float* sTs  = sm + SM_TS;
    float* sX   = sm + SM_X;
    float* sGx  = sm + SM_GX;
    float* sCat = sm + SM_CAT;
    float* sSoa = sm + SM_SOA;
    float* sAtt = sm + SM_ATT;
    __shared__ int sPrev[RPB];
    __shared__ unsigned long long sArg[RPB];

    const int tid = threadIdx.x;
    const int lane = tid & 31, warp = tid >> 5;
    const int b0 = blockIdx.x * RPB;
    const float LT = logf(1e-13f);

    // ---- prologue: load mem, ts, prev
    for (int i = tid; i < RPB*SRCs*Dd; i += 256)
        sMem[i] = mem[(size_t)b0*SRCs*Dd + i];
    for (int i = tid; i < RPB*Dd; i += 256) {
        float v = ts0[b0*Dd + i];
        sTs0[i] = v; sTs[i] = v;
    }
    if (tid < RPB) { sPrev[tid] = lhs[b0 + tid]; sArg[tid] = 0ull; }
    __syncthreads();

    // ---- gh = ts0 @ Wh + bh (per-batch constant)
    {
        float acc[RPB][3];
        #pragma unroll
        for (int r=0;r<RPB;r++) { acc[r][0]=0.f; acc[r][1]=0.f; acc[r][2]=0.f; }
        for (int k = 0; k < Dd; k++) {
            float w0 = Wh[(size_t)k*G3 + tid];
            float w1 = Wh[(size_t)k*G3 + 256 + tid];
            float w2 = Wh[(size_t)k*G3 + 512 + tid];
            #pragma unroll
            for (int r=0;r<RPB;r++) {
                float a = sTs0[r*Dd + k];
                acc[r][0] += a*w0; acc[r][1] += a*w1; acc[r][2] += a*w2;
            }
        }
        #pragma unroll
        for (int r=0;r<RPB;r++) {
            sGh[r*G3 + tid]       = acc[r][0] + bh[tid];
            sGh[r*G3 + 256 + tid] = acc[r][1] + bh[256 + tid];
            sGh[r*G3 + 512 + tid] = acc[r][2] + bh[512 + tid];
        }
    }
    __syncthreads();

    // ---- 10 steps
    for (int t = 0; t < SEQs; t++) {
        // gather x = emb[prev]
        for (int i = tid; i < RPB*Dd; i += 256) {
            int r = i >> 8, k = i & 255;
            sX[i] = emb[(size_t)sPrev[r]*Dd + k];
        }
        __syncthreads();

        // gx = x @ Wx + bx
        {
            float acc[RPB][3];
            #pragma unroll
            for (int r=0;r<RPB;r++) { acc[r][0]=0.f; acc[r][1]=0.f; acc[r][2]=0.f; }
            #pragma unroll 2
            for (int k = 0; k < Dd; k++) {
                float w0 = Wx[(size_t)k*G3 + tid];
                float w1 = Wx[(size_t)k*G3 + 256 + tid];
                float w2 = Wx[(size_t)k*G3 + 512 + tid];
                #pragma unroll
                for (int r=0;r<RPB;r++) {
                    float a = sX[r*Dd + k];
                    acc[r][0] += a*w0; acc[r][1] += a*w1; acc[r][2] += a*w2;
                }
            }
            #pragma unroll
            for (int r=0;r<RPB;r++) {
                sGx[r*G3 + tid]       = acc[r][0] + bx[tid];
                sGx[r*G3 + 256 + tid] = acc[r][1] + bx[256 + tid];
                sGx[r*G3 + 512 + tid] = acc[r][2] + bx[512 + tid];
            }
        }
        __syncthreads();

        // GRU gates -> h (into sCat second half)
        {
            int j = tid;
            #pragma unroll
            for (int r=0;r<RPB;r++) {
                float xr = sGx[r*G3 + j], xz = sGx[r*G3 + 256 + j], xn = sGx[r*G3 + 512 + j];
                float hr = sGh[r*G3 + j], hz = sGh[r*G3 + 256 + j], hn = sGh[r*G3 + 512 + j];
                float rg = 1.f/(1.f + expf(-(xr+hr)));
                float z  = 1.f/(1.f + expf(-(xz+hz)));
                float n  = tanhf(xn + rg*hn);
                sCat[r*512 + 256 + j] = (1.f - z)*n + z*sTs0[r*Dd + j];
            }
        }
        __syncthreads();

        // attention dots: 160 = 4*40, warp-per-dot
        for (int d = warp; d < RPB*SRCs; d += 8) {
            int r = d / SRCs, s = d % SRCs;
            const float* hrow = sCat + r*512 + 256;
            const float* mrow = sMem + (r*SRCs + s)*Dd;
            float sum = 0.f;
            for (int k = lane; k < Dd; k += 32) sum += hrow[k]*mrow[k];
            #pragma unroll
            for (int o=16;o;o>>=1) sum += __shfl_down_sync(0xffffffffu, sum, o);
            if (lane == 0) sAtt[r*SRCs + s] = sum;
        }
        __syncthreads();

        // softmax over 40 per batch; warp r
        if (warp < RPB) {
            int r = warp;
            float v0 = sAtt[r*SRCs + lane];
            float v1 = (lane < 8) ? sAtt[r*SRCs + 32 + lane] : -1e30f;
            float m = fmaxf(v0, v1);
            #pragma unroll
            for (int o=16;o;o>>=1) m = fmaxf(m, __shfl_xor_sync(0xffffffffu, m, o));
            float e0 = expf(v0 - m);
            float e1 = (lane < 8) ? expf(v1 - m) : 0.f;
            float s = e0 + e1;
            #pragma unroll
            for (int o=16;o;o>>=1) s += __shfl_xor_sync(0xffffffffu, s, o);
            float inv = 1.f/s;
            sAtt[r*SRCs + lane] = e0*inv;
            if (lane < 8) sAtt[r*SRCs + 32 + lane] = e1*inv;
        }
        __syncthreads();

        // ctx into sCat first half
        {
            int j = tid;
            #pragma unroll
            for (int r=0;r<RPB;r++) {
                float cx = 0.f;
                #pragma unroll 8
                for (int s=0;s<SRCs;s++) cx += sAtt[r*SRCs + s]*sMem[(r*SRCs + s)*Dd + j];
                sCat[r*512 + j] = cx;
            }
        }
        __syncthreads();

        // soa = tanh(cat @ Wc + bc); ts = tanh(ts + soa)
        {
            float acc[RPB];
            #pragma unroll
            for (int r=0;r<RPB;r++) acc[r] = 0.f;
            #pragma unroll 2
            for (int k = 0; k < 2*Dd; k++) {
                float w = Wc[(size_t)k*Dd + tid];
                #pragma unroll
                for (int r=0;r<RPB;r++) acc[r] += sCat[r*512 + k]*w;
            }
            #pragma unroll
            for (int r=0;r<RPB;r++) {
                float s = tanhf(acc[r] + bc[tid]);
                sSoa[r*Dd + tid] = s;
                sTs[r*Dd + tid] = tanhf(sTs[r*Dd + tid] + s);
            }
        }
        __syncthreads();

        // logits = soa @ Wsym + bsym + mask; store clog; local argmax
        {
            const int c0 = tid*8;
            const bool ok = (c0 < Vv);     // thread covers c0..c0+7 (all < 2000) or none
            float L[8][RPB];
            #pragma unroll
            for (int j=0;j<8;j++) {
                #pragma unroll
                for (int r=0;r<RPB;r++) L[j][r] = 0.f;
            }
            if (ok) {
                #pragma unroll 2
                for (int k = 0; k < Dd; k++) {
                    float a0 = sSoa[k], a1 = sSoa[256+k], a2 = sSoa[512+k], a3 = sSoa[768+k];
                    float4 w0 = *(const float4*)(Wsym + (size_t)k*Vv + c0);
                    float4 w1 = *(const float4*)(Wsym + (size_t)k*Vv + c0 + 4);
                    float wv[8] = {w0.x,w0.y,w0.z,w0.w,w1.x,w1.y,w1.z,w1.w};
                    #pragma unroll
                    for (int j=0;j<8;j++) {
                        L[j][0] += a0*wv[j]; L[j][1] += a1*wv[j];
                        L[j][2] += a2*wv[j]; L[j][3] += a3*wv[j];
                    }
                }
            }
            unsigned long long bestr[RPB];
            #pragma unroll
            for (int r=0;r<RPB;r++) bestr[r] = 0ull;
            if (ok) {
                #pragma unroll
                for (int j=0;j<8;j++) {
                    int c = c0 + j;
                    float bs = bsym[c];
                    #pragma unroll
                    for (int r=0;r<RPB;r++) {
                        int row = t*Bb + b0 + r;
                        float v = L[j][r] + bs;
                        if (!d_w[(size_t)row*Vv + c]) v += LT;
                        d_clog[(size_t)row*Vv + c] = v;
                        unsigned long long key = ((unsigned long long)f2mono(v) << 32)
                                               | (0xFFFFFFFFu - (unsigned)c);
                        if (key > bestr[r]) bestr[r] = key;
                    }
                }
            }
            #pragma unroll
            for (int r=0;r<RPB;r++) {
                unsigned long long bv = bestr[r];
                #pragma unroll
                for (int o=16;o;o>>=1) {
                    unsigned long long x = __shfl_xor_sync(0xffffffffu, bv, o);
                    if (x > bv) bv = x;
                }
                if (lane == 0 && bv) atomicMax(&sArg[r], bv);
            }
        }
        __syncthreads();
        if (tid < RPB) {
            sPrev[tid] = (int)(0xFFFFFFFFu - (unsigned)(sArg[tid] & 0xFFFFFFFFull));
            sArg[tid] = 0ull;
        }
        __syncthreads();
    }

    // write final ts
    for (int i = tid; i < RPB*Dd; i += 256)
        d_ts[b0*Dd + i] = sTs[i];
}

// ============================================================================
// k_tail: per-batch lse + opts + topo + prepA. grid=256.
// ============================================================================
__global__ __launch_bounds__(256) void k_tail(const int* __restrict__ gg,
                                              const float* __restrict__ emb,
                                              float* __restrict__ out)
{
    const int b = blockIdx.x;
    const int tid = threadIdx.x;
    const int lane = tid & 31, warp = tid >> 5;
    __shared__ float sLse[SEQs];
    __shared__ float sVals[OPTo*SEQs];
    __shared__ float sSol[OPTo];
    __shared__ int   sBest;
    __shared__ int   sSym[SEQs];

    for (int t = warp; t < SEQs; t += 8) {
        const float* row = d_clog + ((size_t)t*Bb + b)*Vv;
        float m = -1e30f;
        for (int v = lane; v < Vv; v += 32) m = fmaxf(m, row[v]);
        #pragma unroll
        for (int o=16;o;o>>=1) m = fmaxf(m, __shfl_xor_sync(0xffffffffu, m, o));
        float s = 0.f;
        for (int v = lane; v < Vv; v += 32) s += expf(row[v]-m);
        #pragma unroll
        for (int o=16;o;o>>=1) s += __shfl_xor_sync(0xffffffffu, s, o);
        if (lane == 0) sLse[t] = m + logf(s);
    }
    __syncthreads();
    if (tid < OPTo*SEQs) {
        int o = tid / SEQs, t = tid % SEQs;
        int base = ((b*OPTo + o)*4)*SEQs + t;
        int m = gg[base + 3*SEQs];
        float v = 0.f;
        if (m) {
            int sym = gg[base];
            v = logf(expf(d_clog[((size_t)t*Bb + b)*Vv + sym] - sLse[t]) + 1e-13f);
        }
        sVals[tid] = v;
    }
    __syncthreads();
    if (tid < OPTo) {
        float s = 0.f;
        #pragma unroll
        for (int t=0;t<SEQs;t++) s += sVals[tid*SEQs + t];
        sSol[tid] = s;
        out[OFF_OPT + b*OPTo + tid] = s;
    }
    __syncthreads();
    if (tid == 0) {
        int bi = 0; float bv = sSol[0];
        for (int o=1;o<OPTo;o++) if (sSol[o] > bv) { bv = sSol[o]; bi = o; }
        sBest = bi;
    }
    __syncthreads();
    if (tid < 4*SEQs) {
        int c = tid / SEQs, s = tid % SEQs;
        int val = gg[((b*OPTo + sBest)*4 + c)*SEQs + s];
        out[OFF_TOPO + c*(Bb*SEQs) + b*SEQs + s] = (float)val;
        if (c == 0) { sSym[s] = val; d_sym[b*SEQs + s] = val; }
    }
    __syncthreads();
    // prepA rows for k_exact
    for (int i = tid; i < SEQs*512; i += 256) {
        int s = i >> 9, k = i & 511;
        float v = (k < Dd) ? emb[(size_t)sSym[s]*Dd + k] : d_ts[b*Dd + (k - Dd)];
        d_Ahi[((size_t)b*SEQs + s)*512 + k] = __float2bfloat16(v);
    }
}

// ---------------- exact_logit GEMM: single bf16 mma, 128x128x32, double-buffered --
#define MMA16816(d, a, b) asm volatile( \
    "mma.sync.aligned.m16n8k16.row.col.f32.bf16.bf16.f32 " \
    "{%0,%1,%2,%3}, {%4,%5,%6,%7}, {%8,%9}, {%0,%1,%2,%3};\n" \
    : "+f"(d[0]), "+f"(d[1]), "+f"(d[2]), "+f"(d[3]) \
    : "r"(a[0]), "r"(a[1]), "r"(a[2]), "r"(a[3]), "r"(b[0]), "r"(b[1]))

#define XSTR 40

__global__ __launch_bounds__(256) void k_exact(const float* __restrict__ btok,
                                               const float* __restrict__ tok,
                                               float* __restrict__ out) {
    __shared__ __nv_bfloat16 sA[2][128*XSTR], sB[2][128*XSTR];
    int tid = threadIdx.x;
    int m0 = blockIdx.y*128, n0 = blockIdx.x*128;
    int lane = tid & 31, warp = tid >> 5;
    int wm = warp >> 2, wn = warp & 3;
    int g = lane >> 2, tq = lane & 3;
    float acc[4][4][4];
    #pragma unroll
    for (int i=0;i<4;i++) {
        #pragma unroll
        for (int j=0;j<4;j++) {
            #pragma unroll
            for (int q=0;q<4;q++) acc[i][j][q] = 0.f;
        }
    }

    int row = tid >> 1;
    int kh  = (tid & 1) << 4;
    int nr  = n0 + row;
    const bool nok = (nr < VTt);

    uint4 ra0, ra1, rb0, rb1;
    const uint4 z0 = make_uint4(0,0,0,0);

    {
        const uint4* p = (const uint4*)(d_Ahi + (size_t)(m0+row)*512 + kh);
        ra0 = p[0]; ra1 = p[1];
        rb0 = z0; rb1 = z0;
        if (nok) {
            const uint4* q = (const uint4*)(d_WhiT + (size_t)nr*512 + kh);
            rb0 = q[0]; rb1 = q[1];
        }
    }
    *(uint4*)&sA[0][row*XSTR + kh]     = ra0;
    *(uint4*)&sA[0][row*XSTR + kh + 8] = ra1;
    *(uint4*)&sB[0][row*XSTR + kh]     = rb0;
    *(uint4*)&sB[0][row*XSTR + kh + 8] = rb1;
    __syncthreads();

    int buf = 0;
    for (int k0 = 0; k0 < 512; k0 += 32) {
        int nxt = k0 + 32;
        if (nxt < 512) {
            const uint4* p = (const uint4*)(d_Ahi + (size_t)(m0+row)*512 + nxt + kh);
            ra0 = p[0]; ra1 = p[1];
            rb0 = z0; rb1 = z0;
            if (nok) {
                const uint4* q = (const uint4*)(d_WhiT + (size_t)nr*512 + nxt + kh);
                rb0 = q[0]; rb1 = q[1];
            }
        }
        const __nv_bfloat16* cA = sA[buf];
        const __nv_bfloat16* cB = sB[buf];
        #pragma unroll
        for (int ks = 0; ks < 2; ks++) {
            int kb = ks*16;
            uint32_t ah[4][4];
            #pragma unroll
            for (int mi=0;mi<4;mi++) {
                int rb = wm*64 + mi*16;
                int c0 = kb + tq*2;
                ah[mi][0] = *(const uint32_t*)&cA[(rb+g)*XSTR + c0];
                ah[mi][1] = *(const uint32_t*)&cA[(rb+g+8)*XSTR + c0];
                ah[mi][2] = *(const uint32_t*)&cA[(rb+g)*XSTR + c0 + 8];
                ah[mi][3] = *(const uint32_t*)&cA[(rb+g+8)*XSTR + c0 + 8];
            }
            uint32_t bh[4][2];
            #pragma unroll
            for (int ni=0;ni<4;ni++) {
                int nb = wn*32 + ni*8 + g;
                bh[ni][0] = *(const uint32_t*)&cB[nb*XSTR + kb + tq*2];
                bh[ni][1] = *(const uint32_t*)&cB[nb*XSTR + kb + tq*2 + 8];
            }
            #pragma unroll
            for (int mi=0;mi<4;mi++) {
                #pragma unroll
                for (int ni=0;ni<4;ni++) {
                    MMA16816(acc[mi][ni], ah[mi], bh[ni]);
                }
            }
        }
        if (nxt < 512) {
            *(uint4*)&sA[buf^1][row*XSTR + kh]     = ra0;
            *(uint4*)&sA[buf^1][row*XSTR + kh + 8] = ra1;
            *(uint4*)&sB[buf^1][row*XSTR + kh]     = rb0;
            *(uint4*)&sB[buf^1][row*XSTR + kh + 8] = rb1;
            __syncthreads();
            buf ^= 1;
        }
    }

    const float LT = logf(1e-13f);
    #pragma unroll
    for (int mi=0;mi<4;mi++) {
        int r0 = m0 + wm*64 + mi*16 + g;
        int s0 = d_sym[r0];
        int s1 = d_sym[r0 + 8];
        #pragma unroll
        for (int ni=0;ni<4;ni++) {
            int c0 = n0 + wn*32 + ni*8 + tq*2;
            if (c0 < VTt) {
                float b0 = btok[c0];
                out[OFF_EX + (size_t)r0*VTt + c0]     = acc[mi][ni][0] + b0 + (tok[(size_t)s0*VTt + c0] > 0.f ? 0.f : LT);
                out[OFF_EX + (size_t)(r0+8)*VTt + c0] = acc[mi][ni][2] + b0 + (tok[(size_t)s1*VTt + c0] > 0.f ? 0.f : LT);
            }
            if (c0 + 1 < VTt) {
                float b1 = btok[c0+1];
                out[OFF_EX + (size_t)r0*VTt + c0+1]     = acc[mi][ni][1] + b1 + (tok[(size_t)s0*VTt + c0+1] > 0.f ? 0.f : LT);
                out[OFF_EX + (size_t)(r0+8)*VTt + c0+1] = acc[mi][ni][3] + b1 + (tok[(size_t)s1*VTt + c0+1] > 0.f ? 0.f : LT);
            }
        }
    }
}

// ---------------- host launcher ----------------
extern "C" void kernel_launch(void* const* d_in, const int* in_sizes, int n_in,
                              void* d_out, int out_size) {
    const int*   lhs   = (const int*)d_in[0];
    const int*   lmask = (const int*)d_in[1];
    const float* ts0   = (const float*)d_in[2];
    const int*   gg    = (const int*)d_in[3];
    const float* emb   = (const float*)d_in[4];
    const float* mem   = (const float*)d_in[5];
    const float* Wx    = (const float*)d_in[6];
    const float* Wh    = (const float*)d_in[7];
    const float* bx    = (const float*)d_in[8];
    const float* bh    = (const float*)d_in[9];
    const float* Wc    = (const float*)d_in[10];
    const float* bc    = (const float*)d_in[11];
    const float* Wsym  = (const float*)d_in[12];
    const float* bsym  = (const float*)d_in[13];
    const float* Wtok  = (const float*)d_in[14];
    const float* btok  = (const float*)d_in[15];
    const float* tok   = (const float*)d_in[16];
    float* out = (float*)d_out;

    static bool attr_set = false;
    if (!attr_set) {
        cudaFuncSetAttribute(k_steps, cudaFuncAttributeMaxDynamicSharedMemorySize, SM_BYTES);
        attr_set = true;
    }

    k_w<<<SEQs*Bb, 64>>>(gg);
    k_prepW<<<5008, 256>>>(Wtok);
    k_copy<<<642, 256>>>(lhs, lmask, gg, out);
    k_steps<<<GSTEP, 256, SM_BYTES>>>(lhs, ts0, emb, mem, Wx, bx, Wh, bh, Wc, bc, Wsym, bsym);
    k_tail<<<Bb, 256>>>(gg, emb, out);
    k_exact<<<dim3((VTt+127)/128, (Bb*SEQs)/128), 256>>>(btok, tok, out);
}

// round 7
// speedup vs baseline: 1.8083x; 1.8083x over previous
#include <cuda_runtime.h>
#include <cuda_bf16.h>
#include <cstdint>

#define Bb   256
#define Dd   256
#define Vv   2000
#define VTt  10000
#define OPTo 16
#define SEQs 10
#define SRCs 40
#define G3   768
#define GSTEP 64
#define RPB   4
#define THR   512

#define OFF_OPT  164352
#define OFF_TOPO 168448
#define OFF_EX   178688

// ---------------- device scratch ----------------
__device__ float d_ts[Bb*Dd];
__device__ float d_clog[SEQs*Bb*Vv];
__device__ unsigned char d_w[SEQs*Bb*Vv];
__device__ int   d_sym[Bb*SEQs];
__device__ __nv_bfloat16 d_Ahi[Bb*SEQs*2*Dd];
__device__ __nv_bfloat16 d_WhiT[(size_t)VTt*2*Dd];

__device__ __forceinline__ unsigned f2mono(float f) {
    unsigned u = __float_as_uint(f);
    return (u & 0x80000000u) ? ~u : (u | 0x80000000u);
}

// packed f32x2 helpers (sm_103a)
#define FMA2(d, a, b) asm("fma.rn.f32x2 %0, %1, %2, %0;" : "+l"(d) : "l"(a), "l"(b))
__device__ __forceinline__ unsigned long long pk2(float x, float y) {
    unsigned long long r;
    asm("mov.b64 %0, {%1,%2};" : "=l"(r) : "f"(x), "f"(y));
    return r;
}
__device__ __forceinline__ float2 up2(unsigned long long v) {
    float2 r;
    asm("mov.b64 {%0,%1}, %2;" : "=f"(r.x), "=f"(r.y) : "l"(v));
    return r;
}

// ---------------- grammar w masks ----------------
__global__ void k_w(const int* __restrict__ gg) {
    int tb = blockIdx.x;            // t*B + b
    int t = tb / Bb, b = tb % Bb;
    int tid = threadIdx.x;          // 64 threads
    __shared__ unsigned char ws[Vv];
    __shared__ int f0;
    for (int v = tid; v < Vv; v += 64) ws[v] = 0;
    if (tid == 0) f0 = 0;
    __syncthreads();
    if (tid < OPTo) {
        int base = ((b*OPTo + tid)*4)*SEQs + t;
        int sym = gg[base];
        int m   = gg[base + 3*SEQs];
        if (m) { if (sym > 0) ws[sym] = 1; else f0 = 1; }
    }
    __syncthreads();
    if (tid == 0) ws[0] = (unsigned char)f0;
    __syncthreads();
    unsigned char* outp = d_w + (size_t)tb*Vv;
    for (int v = tid; v < Vv; v += 64) outp[v] = ws[v];
}

// ---------------- copy small outputs ----------------
__global__ void k_copy(const int* __restrict__ lhs, const int* __restrict__ lmask,
                       const int* __restrict__ gg, float* __restrict__ out) {
    for (int i = blockIdx.x*blockDim.x + threadIdx.x; i < OFF_OPT; i += gridDim.x*blockDim.x) {
        if (i < 256)       out[i] = (float)lhs[i];
        else if (i < 512)  out[i] = (float)lmask[i-256];
        else               out[i] = (float)gg[i-512];
    }
}

// ---------------- prep W: Wtok transpose to (VT,512) bf16 ----------------
__global__ void k_prepW(const float* __restrict__ Wtok) {
    __shared__ float tile[32][33];
    int bi = blockIdx.x;
    int tid = threadIdx.x;
    int tx = tid & 31, ty = tid >> 5;   // 32 x 8
    int n0 = (bi % 313)*32, k0 = (bi / 313)*32;
    #pragma unroll
    for (int i=0;i<4;i++) {
        int k = k0 + ty + i*8, n = n0 + tx;
        tile[ty+i*8][tx] = (n < VTt) ? Wtok[(size_t)k*VTt + n] : 0.f;
    }
    __syncthreads();
    #pragma unroll
    for (int i=0;i<4;i++) {
        int n = n0 + ty + i*8, k = k0 + tx;
        if (n < VTt)
            d_WhiT[(size_t)n*512 + k] = __float2bfloat16(tile[tx][ty+i*8]);
    }
}

// ============================================================================
// k_steps: 64 blocks x 4 batches, 512 threads, f32x2 FMA, no grid sync.
// ============================================================================
// dyn smem layout (floats)
#define SM_MEM   0            // 40960
#define SM_GH    40960        // 3072
#define SM_GX    44032        // 3072
#define SM_TS0   47104        // 1024
#define SM_TS    48128        // 1024
#define SM_XP    49152        // 1024  packed [k][4]
#define SM_CATP  50176        // 2048  packed [k][4]
#define SM_SOAP  52224        // 1024  packed [k][4]
#define SM_H     53248        // 1024  unpacked [r][256]
#define SM_ATT   54272        // 160
#define SM_TOT_F 54432
#define SM_BYTES (SM_TOT_F*4)

// sOut[r*768+c] = sum_k xp[k][r] * W[k*768+c] + bias[c] ; threads 0..191 own 4 cols
__device__ __forceinline__ void gemm768_f32x2(const float* __restrict__ W,
                                              const float* __restrict__ bias,
                                              const float* sXp, float* sOut, int tid) {
    if (tid < 192) {
        int c0 = tid*4;
        unsigned long long a01[4] = {0,0,0,0};
        unsigned long long a23[4] = {0,0,0,0};
        for (int k0 = 0; k0 < Dd; k0 += 8) {
            float4 w[8];
            #pragma unroll
            for (int u=0;u<8;u++)
                w[u] = *(const float4*)(W + (size_t)(k0+u)*G3 + c0);
            #pragma unroll
            for (int u=0;u<8;u++) {
                unsigned long long x01 = *(const unsigned long long*)(sXp + (k0+u)*4);
                unsigned long long x23 = *(const unsigned long long*)(sXp + (k0+u)*4 + 2);
                float wv0 = w[u].x, wv1 = w[u].y, wv2 = w[u].z, wv3 = w[u].w;
                unsigned long long p0 = pk2(wv0,wv0), p1 = pk2(wv1,wv1);
                unsigned long long p2 = pk2(wv2,wv2), p3 = pk2(wv3,wv3);
                FMA2(a01[0], x01, p0); FMA2(a23[0], x23, p0);
                FMA2(a01[1], x01, p1); FMA2(a23[1], x23, p1);
                FMA2(a01[2], x01, p2); FMA2(a23[2], x23, p2);
                FMA2(a01[3], x01, p3); FMA2(a23[3], x23, p3);
            }
        }
        #pragma unroll
        for (int j=0;j<4;j++) {
            float bsv = bias[c0+j];
            float2 p01 = up2(a01[j]), p23 = up2(a23[j]);
            sOut[0*G3 + c0+j] = p01.x + bsv;
            sOut[1*G3 + c0+j] = p01.y + bsv;
            sOut[2*G3 + c0+j] = p23.x + bsv;
            sOut[3*G3 + c0+j] = p23.y + bsv;
        }
    }
}

__global__ __launch_bounds__(THR) void k_steps(
    const int* __restrict__ lhs, const float* __restrict__ ts0,
    const float* __restrict__ emb, const float* __restrict__ mem,
    const float* __restrict__ Wx, const float* __restrict__ bx,
    const float* __restrict__ Wh, const float* __restrict__ bh,
    const float* __restrict__ Wc, const float* __restrict__ bc,
    const float* __restrict__ Wsym, const float* __restrict__ bsym)
{
    extern __shared__ float sm[];
    float* sMem  = sm + SM_MEM;
    float* sGh   = sm + SM_GH;
    float* sGx   = sm + SM_GX;
    float* sTs0  = sm + SM_TS0;
    float* sTs   = sm + SM_TS;
    float* sXp   = sm + SM_XP;
    float* sCatP = sm + SM_CATP;
    float* sSoaP = sm + SM_SOAP;
    float* sH    = sm + SM_H;
    float* sAtt  = sm + SM_ATT;
    __shared__ int sPrev[RPB];
    __shared__ unsigned long long sArg[RPB];

    const int tid = threadIdx.x;
    const int lane = tid & 31, warp = tid >> 5;
    const int b0 = blockIdx.x * RPB;
    const float LT = logf(1e-13f);

    // ---- prologue: mem (float4), ts, packed ts0, prev
    {
        const float4* m4 = (const float4*)(mem + (size_t)b0*SRCs*Dd);
        float4* s4 = (float4*)sMem;
        for (int i = tid; i < RPB*SRCs*Dd/4; i += THR) s4[i] = m4[i];
    }
    for (int i = tid; i < RPB*Dd; i += THR) {
        float v = ts0[b0*Dd + i];
        sTs0[i] = v; sTs[i] = v;
        sXp[(i & 255)*4 + (i >> 8)] = v;    // packed ts0 for gh GEMM
    }
    if (tid < RPB) { sPrev[tid] = lhs[b0 + tid]; sArg[tid] = 0ull; }
    __syncthreads();

    // ---- gh = ts0 @ Wh + bh (constant across steps)
    gemm768_f32x2(Wh, bh, sXp, sGh, tid);
    __syncthreads();

    // ---- 10 steps
    for (int t = 0; t < SEQs; t++) {
        // gather x = emb[prev] into packed sXp
        if (tid < 256) {
            int r = tid >> 6, q = tid & 63;
            float4 v = *(const float4*)(emb + (size_t)sPrev[r]*Dd + q*4);
            sXp[(q*4+0)*4 + r] = v.x;
            sXp[(q*4+1)*4 + r] = v.y;
            sXp[(q*4+2)*4 + r] = v.z;
            sXp[(q*4+3)*4 + r] = v.w;
        }
        __syncthreads();

        // gx = x @ Wx + bx
        gemm768_f32x2(Wx, bx, sXp, sGx, tid);
        __syncthreads();

        // GRU gates -> h (sH unpacked + sCatP packed at k=256+j)
        {
            int j = tid & 255, rr = tid >> 8;
            #pragma unroll
            for (int q = 0; q < 2; q++) {
                int r = rr*2 + q;
                float xr = sGx[r*G3 + j], xz = sGx[r*G3 + 256 + j], xn = sGx[r*G3 + 512 + j];
                float hr = sGh[r*G3 + j], hz = sGh[r*G3 + 256 + j], hn = sGh[r*G3 + 512 + j];
                float rg = 1.f/(1.f + expf(-(xr+hr)));
                float z  = 1.f/(1.f + expf(-(xz+hz)));
                float n  = tanhf(xn + rg*hn);
                float h  = (1.f - z)*n + z*sTs0[r*Dd + j];
                sH[r*256 + j] = h;
                sCatP[(256 + j)*4 + r] = h;
            }
        }
        __syncthreads();

        // attention dots: 160 warp-dots over 16 warps
        for (int d = warp; d < RPB*SRCs; d += 16) {
            int r = d / SRCs, s = d % SRCs;
            const float* hrow = sH + r*256;
            const float* mrow = sMem + (r*SRCs + s)*Dd;
            float sum = 0.f;
            #pragma unroll
            for (int k = 0; k < 8; k++) sum += hrow[lane + k*32]*mrow[lane + k*32];
            #pragma unroll
            for (int o=16;o;o>>=1) sum += __shfl_down_sync(0xffffffffu, sum, o);
            if (lane == 0) sAtt[r*SRCs + s] = sum;
        }
        __syncthreads();

        // warp softmax (warps 0..3, one per batch)
        if (warp < RPB) {
            int r = warp;
            float v0 = sAtt[r*SRCs + lane];
            float v1 = (lane < 8) ? sAtt[r*SRCs + 32 + lane] : -1e30f;
            float m = fmaxf(v0, v1);
            #pragma unroll
            for (int o=16;o;o>>=1) m = fmaxf(m, __shfl_xor_sync(0xffffffffu, m, o));
            float e0 = expf(v0 - m);
            float e1 = (lane < 8) ? expf(v1 - m) : 0.f;
            float s = e0 + e1;
            #pragma unroll
            for (int o=16;o;o>>=1) s += __shfl_xor_sync(0xffffffffu, s, o);
            float inv = 1.f/s;
            sAtt[r*SRCs + lane] = e0*inv;
            if (lane < 8) sAtt[r*SRCs + 32 + lane] = e1*inv;
        }
        __syncthreads();

        // ctx into packed sCatP (k = j)
        {
            int j = tid & 255, rr = tid >> 8;
            #pragma unroll
            for (int q = 0; q < 2; q++) {
                int r = rr*2 + q;
                float cx = 0.f;
                #pragma unroll 8
                for (int s=0;s<SRCs;s++) cx += sAtt[r*SRCs + s]*sMem[(r*SRCs + s)*Dd + j];
                sCatP[j*4 + r] = cx;
            }
        }
        __syncthreads();

        // soa = tanh(cat @ Wc + bc), split-k over 512 threads
        {
            int c = tid & 255;
            int kh = (tid >> 8) * 256;
            unsigned long long a01 = 0, a23 = 0;
            for (int k0 = kh; k0 < kh + 256; k0 += 8) {
                float w[8];
                #pragma unroll
                for (int u=0;u<8;u++) w[u] = Wc[(size_t)(k0+u)*Dd + c];
                #pragma unroll
                for (int u=0;u<8;u++) {
                    unsigned long long x01 = *(const unsigned long long*)(sCatP + (k0+u)*4);
                    unsigned long long x23 = *(const unsigned long long*)(sCatP + (k0+u)*4 + 2);
                    unsigned long long wp = pk2(w[u], w[u]);
                    FMA2(a01, x01, wp); FMA2(a23, x23, wp);
                }
            }
            if (tid >= 256) {
                *(unsigned long long*)(sXp + c*4)     = a01;
                *(unsigned long long*)(sXp + c*4 + 2) = a23;
            }
            __syncthreads();
            if (tid < 256) {
                unsigned long long b01 = *(const unsigned long long*)(sXp + c*4);
                unsigned long long b23 = *(const unsigned long long*)(sXp + c*4 + 2);
                float2 p01 = up2(a01), p23 = up2(a23);
                float2 q01 = up2(b01), q23 = up2(b23);
                float bcv = bc[c];
                float s0 = tanhf(p01.x + q01.x + bcv);
                float s1 = tanhf(p01.y + q01.y + bcv);
                float s2 = tanhf(p23.x + q23.x + bcv);
                float s3 = tanhf(p23.y + q23.y + bcv);
                sSoaP[c*4 + 0] = s0; sSoaP[c*4 + 1] = s1;
                sSoaP[c*4 + 2] = s2; sSoaP[c*4 + 3] = s3;
                sTs[0*256 + c] = tanhf(sTs[0*256 + c] + s0);
                sTs[1*256 + c] = tanhf(sTs[1*256 + c] + s1);
                sTs[2*256 + c] = tanhf(sTs[2*256 + c] + s2);
                sTs[3*256 + c] = tanhf(sTs[3*256 + c] + s3);
            }
        }
        __syncthreads();

        // logits = soa @ Wsym + bsym + mask; store clog; argmax
        {
            unsigned long long best[RPB] = {0ull,0ull,0ull,0ull};
            if (tid < 500) {
                int c0 = tid*4;
                unsigned long long a01[4] = {0,0,0,0};
                unsigned long long a23[4] = {0,0,0,0};
                for (int k0 = 0; k0 < Dd; k0 += 4) {
                    float4 w[4];
                    #pragma unroll
                    for (int u=0;u<4;u++)
                        w[u] = *(const float4*)(Wsym + (size_t)(k0+u)*Vv + c0);
                    #pragma unroll
                    for (int u=0;u<4;u++) {
                        unsigned long long x01 = *(const unsigned long long*)(sSoaP + (k0+u)*4);
                        unsigned long long x23 = *(const unsigned long long*)(sSoaP + (k0+u)*4 + 2);
                        unsigned long long p0 = pk2(w[u].x, w[u].x), p1 = pk2(w[u].y, w[u].y);
                        unsigned long long p2 = pk2(w[u].z, w[u].z), p3 = pk2(w[u].w, w[u].w);
                        FMA2(a01[0], x01, p0); FMA2(a23[0], x23, p0);
                        FMA2(a01[1], x01, p1); FMA2(a23[1], x23, p1);
                        FMA2(a01[2], x01, p2); FMA2(a23[2], x23, p2);
                        FMA2(a01[3], x01, p3); FMA2(a23[3], x23, p3);
                    }
                }
                float4 bs = *(const float4*)(bsym + c0);
                float vb[4] = {bs.x, bs.y, bs.z, bs.w};
                float vr[RPB][4];
                #pragma unroll
                for (int j=0;j<4;j++) {
                    float2 p01 = up2(a01[j]), p23 = up2(a23[j]);
                    vr[0][j] = p01.x + vb[j];
                    vr[1][j] = p01.y + vb[j];
                    vr[2][j] = p23.x + vb[j];
                    vr[3][j] = p23.y + vb[j];
                }
                #pragma unroll
                for (int r=0;r<RPB;r++) {
                    int row = t*Bb + b0 + r;
                    uchar4 wm = *(const uchar4*)(d_w + (size_t)row*Vv + c0);
                    unsigned char wmv[4] = {wm.x, wm.y, wm.z, wm.w};
                    float4 st;
                    float* stp = &st.x;
                    #pragma unroll
                    for (int j=0;j<4;j++) {
                        float v = vr[r][j];
                        if (!wmv[j]) v += LT;
                        stp[j] = v;
                        unsigned long long key = ((unsigned long long)f2mono(v) << 32)
                                               | (0xFFFFFFFFu - (unsigned)(c0 + j));
                        if (key > best[r]) best[r] = key;
                    }
                    *(float4*)(d_clog + (size_t)row*Vv + c0) = st;
                }
            }
            #pragma unroll
            for (int r=0;r<RPB;r++) {
                unsigned long long bv = best[r];
                #pragma unroll
                for (int o=16;o;o>>=1) {
                    unsigned long long x = __shfl_xor_sync(0xffffffffu, bv, o);
                    if (x > bv) bv = x;
                }
                if (lane == 0 && bv) atomicMax(&sArg[r], bv);
            }
        }
        __syncthreads();
        if (tid < RPB) {
            sPrev[tid] = (int)(0xFFFFFFFFu - (unsigned)(sArg[tid] & 0xFFFFFFFFull));
            sArg[tid] = 0ull;
        }
        __syncthreads();
    }

    // write final ts
    for (int i = tid; i < RPB*Dd; i += THR)
        d_ts[b0*Dd + i] = sTs[i];
}

// ============================================================================
// k_tail: per-batch lse + opts + topo + prepA. grid=256.
// ============================================================================
__global__ __launch_bounds__(256) void k_tail(const int* __restrict__ gg,
                                              const float* __restrict__ emb,
                                              float* __restrict__ out)
{
    const int b = blockIdx.x;
    const int tid = threadIdx.x;
    const int lane = tid & 31, warp = tid >> 5;
    __shared__ float sLse[SEQs];
    __shared__ float sVals[OPTo*SEQs];
    __shared__ float sSol[OPTo];
    __shared__ int   sBest;
    __shared__ int   sSym[SEQs];

    for (int t = warp; t < SEQs; t += 8) {
        const float* row = d_clog + ((size_t)t*Bb + b)*Vv;
        float m = -1e30f;
        for (int v = lane; v < Vv; v += 32) m = fmaxf(m, row[v]);
        #pragma unroll
        for (int o=16;o;o>>=1) m = fmaxf(m, __shfl_xor_sync(0xffffffffu, m, o));
        float s = 0.f;
        for (int v = lane; v < Vv; v += 32) s += expf(row[v]-m);
        #pragma unroll
        for (int o=16;o;o>>=1) s += __shfl_xor_sync(0xffffffffu, s, o);
        if (lane == 0) sLse[t] = m + logf(s);
    }
    __syncthreads();
    if (tid < OPTo*SEQs) {
        int o = tid / SEQs, t = tid % SEQs;
        int base = ((b*OPTo + o)*4)*SEQs + t;
        int m = gg[base + 3*SEQs];
        float v = 0.f;
        if (m) {
            int sym = gg[base];
            v = logf(expf(d_clog[((size_t)t*Bb + b)*Vv + sym] - sLse[t]) + 1e-13f);
        }
        sVals[tid] = v;
    }
    __syncthreads();
    if (tid < OPTo) {
        float s = 0.f;
        #pragma unroll
        for (int t=0;t<SEQs;t++) s += sVals[tid*SEQs + t];
        sSol[tid] = s;
        out[OFF_OPT + b*OPTo + tid] = s;
    }
    __syncthreads();
    if (tid == 0) {
        int bi = 0; float bv = sSol[0];
        for (int o=1;o<OPTo;o++) if (sSol[o] > bv) { bv = sSol[o]; bi = o; }
        sBest = bi;
    }
    __syncthreads();
    if (tid < 4*SEQs) {
        int c = tid / SEQs, s = tid % SEQs;
        int val = gg[((b*OPTo + sBest)*4 + c)*SEQs + s];
        out[OFF_TOPO + c*(Bb*SEQs) + b*SEQs + s] = (float)val;
        if (c == 0) { sSym[s] = val; d_sym[b*SEQs + s] = val; }
    }
    __syncthreads();
    for (int i = tid; i < SEQs*512; i += 256) {
        int s = i >> 9, k = i & 511;
        float v = (k < Dd) ? emb[(size_t)sSym[s]*Dd + k] : d_ts[b*Dd + (k - Dd)];
        d_Ahi[((size_t)b*SEQs + s)*512 + k] = __float2bfloat16(v);
    }
}

// ---------------- exact_logit GEMM: single bf16 mma, 128x128x32, double-buffered --
#define MMA16816(d, a, b) asm volatile( \
    "mma.sync.aligned.m16n8k16.row.col.f32.bf16.bf16.f32 " \
    "{%0,%1,%2,%3}, {%4,%5,%6,%7}, {%8,%9}, {%0,%1,%2,%3};\n" \
    : "+f"(d[0]), "+f"(d[1]), "+f"(d[2]), "+f"(d[3]) \
    : "r"(a[0]), "r"(a[1]), "r"(a[2]), "r"(a[3]), "r"(b[0]), "r"(b[1]))

#define XSTR 40

__global__ __launch_bounds__(256) void k_exact(const float* __restrict__ btok,
                                               const float* __restrict__ tok,
                                               float* __restrict__ out) {
    __shared__ __nv_bfloat16 sA[2][128*XSTR], sB[2][128*XSTR];
    int tid = threadIdx.x;
    int m0 = blockIdx.y*128, n0 = blockIdx.x*128;
    int lane = tid & 31, warp = tid >> 5;
    int wm = warp >> 2, wn = warp & 3;
    int g = lane >> 2, tq = lane & 3;
    float acc[4][4][4];
    #pragma unroll
    for (int i=0;i<4;i++) {
        #pragma unroll
        for (int j=0;j<4;j++) {
            #pragma unroll
            for (int q=0;q<4;q++) acc[i][j][q] = 0.f;
        }
    }

    int row = tid >> 1;
    int kh  = (tid & 1) << 4;
    int nr  = n0 + row;
    const bool nok = (nr < VTt);

    uint4 ra0, ra1, rb0, rb1;
    const uint4 z0 = make_uint4(0,0,0,0);

    {
        const uint4* p = (const uint4*)(d_Ahi + (size_t)(m0+row)*512 + kh);
        ra0 = p[0]; ra1 = p[1];
        rb0 = z0; rb1 = z0;
        if (nok) {
            const uint4* q = (const uint4*)(d_WhiT + (size_t)nr*512 + kh);
            rb0 = q[0]; rb1 = q[1];
        }
    }
    *(uint4*)&sA[0][row*XSTR + kh]     = ra0;
    *(uint4*)&sA[0][row*XSTR + kh + 8] = ra1;
    *(uint4*)&sB[0][row*XSTR + kh]     = rb0;
    *(uint4*)&sB[0][row*XSTR + kh + 8] = rb1;
    __syncthreads();

    int buf = 0;
    for (int k0 = 0; k0 < 512; k0 += 32) {
        int nxt = k0 + 32;
        if (nxt < 512) {
            const uint4* p = (const uint4*)(d_Ahi + (size_t)(m0+row)*512 + nxt + kh);
            ra0 = p[0]; ra1 = p[1];
            rb0 = z0; rb1 = z0;
            if (nok) {
                const uint4* q = (const uint4*)(d_WhiT + (size_t)nr*512 + nxt + kh);
                rb0 = q[0]; rb1 = q[1];
            }
        }
        const __nv_bfloat16* cA = sA[buf];
        const __nv_bfloat16* cB = sB[buf];
        #pragma unroll
        for (int ks = 0; ks < 2; ks++) {
            int kb = ks*16;
            uint32_t ah[4][4];
            #pragma unroll
            for (int mi=0;mi<4;mi++) {
                int rb = wm*64 + mi*16;
                int c0 = kb + tq*2;
                ah[mi][0] = *(const uint32_t*)&cA[(rb+g)*XSTR + c0];
                ah[mi][1] = *(const uint32_t*)&cA[(rb+g+8)*XSTR + c0];
                ah[mi][2] = *(const uint32_t*)&cA[(rb+g)*XSTR + c0 + 8];
                ah[mi][3] = *(const uint32_t*)&cA[(rb+g+8)*XSTR + c0 + 8];
            }
            uint32_t bh[4][2];
            #pragma unroll
            for (int ni=0;ni<4;ni++) {
                int nb = wn*32 + ni*8 + g;
                bh[ni][0] = *(const uint32_t*)&cB[nb*XSTR + kb + tq*2];
                bh[ni][1] = *(const uint32_t*)&cB[nb*XSTR + kb + tq*2 + 8];
            }
            #pragma unroll
            for (int mi=0;mi<4;mi++) {
                #pragma unroll
                for (int ni=0;ni<4;ni++) {
                    MMA16816(acc[mi][ni], ah[mi], bh[ni]);
                }
            }
        }
        if (nxt < 512) {
            *(uint4*)&sA[buf^1][row*XSTR + kh]     = ra0;
            *(uint4*)&sA[buf^1][row*XSTR + kh + 8] = ra1;
            *(uint4*)&sB[buf^1][row*XSTR + kh]     = rb0;
            *(uint4*)&sB[buf^1][row*XSTR + kh + 8] = rb1;
            __syncthreads();
            buf ^= 1;
        }
    }

    const float LT = logf(1e-13f);
    #pragma unroll
    for (int mi=0;mi<4;mi++) {
        int r0 = m0 + wm*64 + mi*16 + g;
        int s0 = d_sym[r0];
        int s1 = d_sym[r0 + 8];
        #pragma unroll
        for (int ni=0;ni<4;ni++) {
            int c0 = n0 + wn*32 + ni*8 + tq*2;
            if (c0 < VTt) {
                float b0 = btok[c0];
                out[OFF_EX + (size_t)r0*VTt + c0]     = acc[mi][ni][0] + b0 + (tok[(size_t)s0*VTt + c0] > 0.f ? 0.f : LT);
                out[OFF_EX + (size_t)(r0+8)*VTt + c0] = acc[mi][ni][2] + b0 + (tok[(size_t)s1*VTt + c0] > 0.f ? 0.f : LT);
            }
            if (c0 + 1 < VTt) {
                float b1 = btok[c0+1];
                out[OFF_EX + (size_t)r0*VTt + c0+1]     = acc[mi][ni][1] + b1 + (tok[(size_t)s0*VTt + c0+1] > 0.f ? 0.f : LT);
                out[OFF_EX + (size_t)(r0+8)*VTt + c0+1] = acc[mi][ni][3] + b1 + (tok[(size_t)s1*VTt + c0+1] > 0.f ? 0.f : LT);
            }
        }
    }
}

// ---------------- host launcher ----------------
extern "C" void kernel_launch(void* const* d_in, const int* in_sizes, int n_in,
                              void* d_out, int out_size) {
    const int*   lhs   = (const int*)d_in[0];
    const int*   lmask = (const int*)d_in[1];
    const float* ts0   = (const float*)d_in[2];
    const int*   gg    = (const int*)d_in[3];
    const float* emb   = (const float*)d_in[4];
    const float* mem   = (const float*)d_in[5];
    const float* Wx    = (const float*)d_in[6];
    const float* Wh    = (const float*)d_in[7];
    const float* bx    = (const float*)d_in[8];
    const float* bh    = (const float*)d_in[9];
    const float* Wc    = (const float*)d_in[10];
    const float* bc    = (const float*)d_in[11];
    const float* Wsym  = (const float*)d_in[12];
    const float* bsym  = (const float*)d_in[13];
    const float* Wtok  = (const float*)d_in[14];
    const float* btok  = (const float*)d_in[15];
    const float* tok   = (const float*)d_in[16];
    float* out = (float*)d_out;

    static bool attr_set = false;
    if (!attr_set) {
        cudaFuncSetAttribute(k_steps, cudaFuncAttributeMaxDynamicSharedMemorySize, SM_BYTES);
        attr_set = true;
    }

    k_w<<<SEQs*Bb, 64>>>(gg);
    k_prepW<<<5008, 256>>>(Wtok);
    k_copy<<<642, 256>>>(lhs, lmask, gg, out);
    k_steps<<<GSTEP, THR, SM_BYTES>>>(lhs, ts0, emb, mem, Wx, bx, Wh, bh, Wc, bc, Wsym, bsym);
    k_tail<<<Bb, 256>>>(gg, emb, out);
    k_exact<<<dim3((VTt+127)/128, (Bb*SEQs)/128), 256>>>(btok, tok, out);
}

// round 8
// speedup vs baseline: 3.0030x; 1.6607x over previous
#include <cuda_runtime.h>
#include <cuda_bf16.h>
#include <cstdint>

#define Bb   256
#define Dd   256
#define Vv   2000
#define VTt  10000
#define OPTo 16
#define SEQs 10
#define SRCs 40
#define G3   768
#define GSTEP 64
#define RPB   4
#define THR   512

#define OFF_OPT  164352
#define OFF_TOPO 168448
#define OFF_EX   178688

typedef unsigned long long ull;

// ---------------- device scratch ----------------
__device__ float d_ts[Bb*Dd];
__device__ float d_clog[SEQs*Bb*Vv];
__device__ unsigned char d_w[SEQs*Bb*Vv];
__device__ int   d_sym[Bb*SEQs];
__device__ __nv_bfloat16 d_Ahi[Bb*SEQs*2*Dd];
__device__ __nv_bfloat16 d_WhiT[(size_t)VTt*2*Dd];

__device__ __forceinline__ unsigned f2mono(float f) {
    unsigned u = __float_as_uint(f);
    return (u & 0x80000000u) ? ~u : (u | 0x80000000u);
}

// packed f32x2 helpers (sm_103a)
#define FMA2(d, a, b) asm("fma.rn.f32x2 %0, %1, %2, %0;" : "+l"(d) : "l"(a), "l"(b))
__device__ __forceinline__ ull pk2(float x, float y) {
    ull r;
    asm("mov.b64 %0, {%1,%2};" : "=l"(r) : "f"(x), "f"(y));
    return r;
}
__device__ __forceinline__ float2 up2(ull v) {
    float2 r;
    asm("mov.b64 {%0,%1}, %2;" : "=f"(r.x), "=f"(r.y) : "l"(v));
    return r;
}

// ---------------- grammar w masks ----------------
__global__ void k_w(const int* __restrict__ gg) {
    int tb = blockIdx.x;
    int t = tb / Bb, b = tb % Bb;
    int tid = threadIdx.x;
    __shared__ unsigned char ws[Vv];
    __shared__ int f0;
    for (int v = tid; v < Vv; v += 64) ws[v] = 0;
    if (tid == 0) f0 = 0;
    __syncthreads();
    if (tid < OPTo) {
        int base = ((b*OPTo + tid)*4)*SEQs + t;
        int sym = gg[base];
        int m   = gg[base + 3*SEQs];
        if (m) { if (sym > 0) ws[sym] = 1; else f0 = 1; }
    }
    __syncthreads();
    if (tid == 0) ws[0] = (unsigned char)f0;
    __syncthreads();
    unsigned char* outp = d_w + (size_t)tb*Vv;
    for (int v = tid; v < Vv; v += 64) outp[v] = ws[v];
}

// ---------------- copy small outputs ----------------
__global__ void k_copy(const int* __restrict__ lhs, const int* __restrict__ lmask,
                       const int* __restrict__ gg, float* __restrict__ out) {
    for (int i = blockIdx.x*blockDim.x + threadIdx.x; i < OFF_OPT; i += gridDim.x*blockDim.x) {
        if (i < 256)       out[i] = (float)lhs[i];
        else if (i < 512)  out[i] = (float)lmask[i-256];
        else               out[i] = (float)gg[i-512];
    }
}

// ---------------- prep W: Wtok transpose to (VT,512) bf16 ----------------
__global__ void k_prepW(const float* __restrict__ Wtok) {
    __shared__ float tile[32][33];
    int bi = blockIdx.x;
    int tid = threadIdx.x;
    int tx = tid & 31, ty = tid >> 5;
    int n0 = (bi % 313)*32, k0 = (bi / 313)*32;
    #pragma unroll
    for (int i=0;i<4;i++) {
        int k = k0 + ty + i*8, n = n0 + tx;
        tile[ty+i*8][tx] = (n < VTt) ? Wtok[(size_t)k*VTt + n] : 0.f;
    }
    __syncthreads();
    #pragma unroll
    for (int i=0;i<4;i++) {
        int n = n0 + ty + i*8, k = k0 + tx;
        if (n < VTt)
            d_WhiT[(size_t)n*512 + k] = __float2bfloat16(tile[tx][ty+i*8]);
    }
}

// ============================================================================
// k_steps: 64 blocks x 4 batches, 512 threads, pipelined f32x2 streaming GEMMs.
// ============================================================================
#define SM_MEM   0            // 40960
#define SM_GH    40960        // 3072
#define SM_GX    44032        // 3072   (also soa-phase scratch: dead then)
#define SM_TS0   47104        // 1024
#define SM_TS    48128        // 1024
#define SM_XP    49152        // 1024  packed [k][4]
#define SM_CATP  50176        // 2048  packed [k][4]
#define SM_SOAP  52224        // 1024  packed [k][4]
#define SM_H     53248        // 1024  unpacked [r][256]
#define SM_ATT   54272        // 160
#define SM_TOT_F 54432
#define SM_BYTES (SM_TOT_F*4)

// N=768 GEMM, 2-way k split over threads 0..383; pipelined float4 weight stream.
// Contains __syncthreads — call from ALL threads.
__device__ __forceinline__ void gemm768_ks2(const float* __restrict__ W,
                                            const float* __restrict__ bias,
                                            const float* sXp, float* sOut, int tid) {
    const int active = (tid < 384);
    const int half = (tid >= 192) ? 1 : 0;
    const int c0 = (active ? (half ? tid - 192 : tid) : 0) * 4;
    const int kb = half * 128;
    ull a01[4] = {0,0,0,0}, a23[4] = {0,0,0,0};
    if (active) {
        float4 wA[8], wB[8];
        #pragma unroll
        for (int u=0;u<8;u++) wA[u] = *(const float4*)(W + (size_t)(kb+u)*G3 + c0);
        for (int it = 0; it < 8; ++it) {
            int kA = kb + it*16;
            #pragma unroll
            for (int u=0;u<8;u++) wB[u] = *(const float4*)(W + (size_t)(kA+8+u)*G3 + c0);
            #pragma unroll
            for (int u=0;u<8;u++) {
                ull x01 = *(const ull*)(sXp + (kA+u)*4);
                ull x23 = *(const ull*)(sXp + (kA+u)*4 + 2);
                ull p0 = pk2(wA[u].x,wA[u].x), p1 = pk2(wA[u].y,wA[u].y);
                ull p2 = pk2(wA[u].z,wA[u].z), p3 = pk2(wA[u].w,wA[u].w);
                FMA2(a01[0],x01,p0); FMA2(a23[0],x23,p0);
                FMA2(a01[1],x01,p1); FMA2(a23[1],x23,p1);
                FMA2(a01[2],x01,p2); FMA2(a23[2],x23,p2);
                FMA2(a01[3],x01,p3); FMA2(a23[3],x23,p3);
            }
            int kAn = (it < 7) ? kA + 16 : kb;
            #pragma unroll
            for (int u=0;u<8;u++) wA[u] = *(const float4*)(W + (size_t)(kAn+u)*G3 + c0);
            #pragma unroll
            for (int u=0;u<8;u++) {
                ull x01 = *(const ull*)(sXp + (kA+8+u)*4);
                ull x23 = *(const ull*)(sXp + (kA+8+u)*4 + 2);
                ull p0 = pk2(wB[u].x,wB[u].x), p1 = pk2(wB[u].y,wB[u].y);
                ull p2 = pk2(wB[u].z,wB[u].z), p3 = pk2(wB[u].w,wB[u].w);
                FMA2(a01[0],x01,p0); FMA2(a23[0],x23,p0);
                FMA2(a01[1],x01,p1); FMA2(a23[1],x23,p1);
                FMA2(a01[2],x01,p2); FMA2(a23[2],x23,p2);
                FMA2(a01[3],x01,p3); FMA2(a23[3],x23,p3);
            }
        }
    }
    if (active && half) {
        #pragma unroll
        for (int j=0;j<4;j++) {
            float2 p01 = up2(a01[j]), p23 = up2(a23[j]);
            sOut[0*G3+c0+j] = p01.x; sOut[1*G3+c0+j] = p01.y;
            sOut[2*G3+c0+j] = p23.x; sOut[3*G3+c0+j] = p23.y;
        }
    }
    __syncthreads();
    if (active && !half) {
        #pragma unroll
        for (int j=0;j<4;j++) {
            float bv = bias[c0+j];
            float2 p01 = up2(a01[j]), p23 = up2(a23[j]);
            sOut[0*G3+c0+j] = sOut[0*G3+c0+j] + p01.x + bv;
            sOut[1*G3+c0+j] = sOut[1*G3+c0+j] + p01.y + bv;
            sOut[2*G3+c0+j] = sOut[2*G3+c0+j] + p23.x + bv;
            sOut[3*G3+c0+j] = sOut[3*G3+c0+j] + p23.y + bv;
        }
    }
    __syncthreads();
}

__global__ __launch_bounds__(THR) void k_steps(
    const int* __restrict__ lhs, const float* __restrict__ ts0,
    const float* __restrict__ emb, const float* __restrict__ mem,
    const float* __restrict__ Wx, const float* __restrict__ bx,
    const float* __restrict__ Wh, const float* __restrict__ bh,
    const float* __restrict__ Wc, const float* __restrict__ bc,
    const float* __restrict__ Wsym, const float* __restrict__ bsym)
{
    extern __shared__ float sm[];
    float* sMem  = sm + SM_MEM;
    float* sGh   = sm + SM_GH;
    float* sGx   = sm + SM_GX;
    float* sTs0  = sm + SM_TS0;
    float* sTs   = sm + SM_TS;
    float* sXp   = sm + SM_XP;
    float* sCatP = sm + SM_CATP;
    float* sSoaP = sm + SM_SOAP;
    float* sH    = sm + SM_H;
    float* sAtt  = sm + SM_ATT;
    __shared__ int sPrev[RPB];
    __shared__ unsigned long long sArg[RPB];

    const int tid = threadIdx.x;
    const int lane = tid & 31, warp = tid >> 5;
    const int b0 = blockIdx.x * RPB;
    const float LT = logf(1e-13f);

    // ---- prologue
    {
        const float4* m4 = (const float4*)(mem + (size_t)b0*SRCs*Dd);
        float4* s4 = (float4*)sMem;
        for (int i = tid; i < RPB*SRCs*Dd/4; i += THR) s4[i] = m4[i];
    }
    for (int i = tid; i < RPB*Dd; i += THR) {
        float v = ts0[b0*Dd + i];
        sTs0[i] = v; sTs[i] = v;
        sXp[(i & 255)*4 + (i >> 8)] = v;
    }
    if (tid < RPB) { sPrev[tid] = lhs[b0 + tid]; sArg[tid] = 0ull; }
    __syncthreads();

    // gh = ts0 @ Wh + bh (constant across steps)
    gemm768_ks2(Wh, bh, sXp, sGh, tid);

    // ---- 10 steps
    for (int t = 0; t < SEQs; t++) {
        // gather x = emb[prev] packed
        if (tid < 256) {
            int r = tid >> 6, q = tid & 63;
            float4 v = *(const float4*)(emb + (size_t)sPrev[r]*Dd + q*4);
            sXp[(q*4+0)*4 + r] = v.x;
            sXp[(q*4+1)*4 + r] = v.y;
            sXp[(q*4+2)*4 + r] = v.z;
            sXp[(q*4+3)*4 + r] = v.w;
        }
        __syncthreads();

        // gx = x @ Wx + bx  (pipelined, 384 threads)
        gemm768_ks2(Wx, bx, sXp, sGx, tid);

        // GRU gates -> h
        {
            int j = tid & 255, rr = tid >> 8;
            #pragma unroll
            for (int q = 0; q < 2; q++) {
                int r = rr*2 + q;
                float xr = sGx[r*G3 + j], xz = sGx[r*G3 + 256 + j], xn = sGx[r*G3 + 512 + j];
                float hr = sGh[r*G3 + j], hz = sGh[r*G3 + 256 + j], hn = sGh[r*G3 + 512 + j];
                float rg = 1.f/(1.f + expf(-(xr+hr)));
                float z  = 1.f/(1.f + expf(-(xz+hz)));
                float n  = tanhf(xn + rg*hn);
                float h  = (1.f - z)*n + z*sTs0[r*Dd + j];
                sH[r*256 + j] = h;
                sCatP[(256 + j)*4 + r] = h;
            }
        }
        __syncthreads();

        // attention dots
        for (int d = warp; d < RPB*SRCs; d += 16) {
            int r = d / SRCs, s = d % SRCs;
            const float* hrow = sH + r*256;
            const float* mrow = sMem + (r*SRCs + s)*Dd;
            float sum = 0.f;
            #pragma unroll
            for (int k = 0; k < 8; k++) sum += hrow[lane + k*32]*mrow[lane + k*32];
            #pragma unroll
            for (int o=16;o;o>>=1) sum += __shfl_down_sync(0xffffffffu, sum, o);
            if (lane == 0) sAtt[r*SRCs + s] = sum;
        }
        __syncthreads();

        // softmax (warps 0..3)
        if (warp < RPB) {
            int r = warp;
            float v0 = sAtt[r*SRCs + lane];
            float v1 = (lane < 8) ? sAtt[r*SRCs + 32 + lane] : -1e30f;
            float m = fmaxf(v0, v1);
            #pragma unroll
            for (int o=16;o;o>>=1) m = fmaxf(m, __shfl_xor_sync(0xffffffffu, m, o));
            float e0 = expf(v0 - m);
            float e1 = (lane < 8) ? expf(v1 - m) : 0.f;
            float s = e0 + e1;
            #pragma unroll
            for (int o=16;o;o>>=1) s += __shfl_xor_sync(0xffffffffu, s, o);
            float inv = 1.f/s;
            sAtt[r*SRCs + lane] = e0*inv;
            if (lane < 8) sAtt[r*SRCs + 32 + lane] = e1*inv;
        }
        __syncthreads();

        // ctx packed
        {
            int j = tid & 255, rr = tid >> 8;
            #pragma unroll
            for (int q = 0; q < 2; q++) {
                int r = rr*2 + q;
                float cx = 0.f;
                #pragma unroll 8
                for (int s=0;s<SRCs;s++) cx += sAtt[r*SRCs + s]*sMem[(r*SRCs + s)*Dd + j];
                sCatP[j*4 + r] = cx;
            }
        }
        __syncthreads();

        // soa = tanh(cat @ Wc + bc); 4-way k-split, float2 loads, pipelined
        {
            const int sp = tid >> 7;        // 0..3
            const int cg = tid & 127;
            const int c0 = cg*2;
            const int kb = sp*128;
            ull a01[2] = {0,0}, a23[2] = {0,0};
            {
                float2 wA[8], wB[8];
                #pragma unroll
                for (int u=0;u<8;u++) wA[u] = *(const float2*)(Wc + (size_t)(kb+u)*Dd + c0);
                for (int it = 0; it < 8; ++it) {
                    int kA = kb + it*16;
                    #pragma unroll
                    for (int u=0;u<8;u++) wB[u] = *(const float2*)(Wc + (size_t)(kA+8+u)*Dd + c0);
                    #pragma unroll
                    for (int u=0;u<8;u++) {
                        ull x01 = *(const ull*)(sCatP + (kA+u)*4);
                        ull x23 = *(const ull*)(sCatP + (kA+u)*4 + 2);
                        ull p0 = pk2(wA[u].x,wA[u].x), p1 = pk2(wA[u].y,wA[u].y);
                        FMA2(a01[0],x01,p0); FMA2(a23[0],x23,p0);
                        FMA2(a01[1],x01,p1); FMA2(a23[1],x23,p1);
                    }
                    int kAn = (it < 7) ? kA + 16 : kb;
                    #pragma unroll
                    for (int u=0;u<8;u++) wA[u] = *(const float2*)(Wc + (size_t)(kAn+u)*Dd + c0);
                    #pragma unroll
                    for (int u=0;u<8;u++) {
                        ull x01 = *(const ull*)(sCatP + (kA+8+u)*4);
                        ull x23 = *(const ull*)(sCatP + (kA+8+u)*4 + 2);
                        ull p0 = pk2(wB[u].x,wB[u].x), p1 = pk2(wB[u].y,wB[u].y);
                        FMA2(a01[0],x01,p0); FMA2(a23[0],x23,p0);
                        FMA2(a01[1],x01,p1); FMA2(a23[1],x23,p1);
                    }
                }
            }
            if (sp > 0) {
                float* scr = sGx + (sp-1)*1024;   // sGx dead here; 3*1024 floats scratch
                #pragma unroll
                for (int j=0;j<2;j++) {
                    float2 p01 = up2(a01[j]), p23 = up2(a23[j]);
                    scr[(c0+j)*4+0] = p01.x; scr[(c0+j)*4+1] = p01.y;
                    scr[(c0+j)*4+2] = p23.x; scr[(c0+j)*4+3] = p23.y;
                }
            }
            __syncthreads();
            if (sp == 0) {
                #pragma unroll
                for (int j=0;j<2;j++) {
                    float2 p01 = up2(a01[j]), p23 = up2(a23[j]);
                    float v[4] = {p01.x, p01.y, p23.x, p23.y};
                    float bcv = bc[c0+j];
                    #pragma unroll
                    for (int r=0;r<4;r++) {
                        float sum = v[r] + sGx[0*1024+(c0+j)*4+r]
                                         + sGx[1*1024+(c0+j)*4+r]
                                         + sGx[2*1024+(c0+j)*4+r] + bcv;
                        float s = tanhf(sum);
                        sSoaP[(c0+j)*4+r] = s;
                        sTs[r*256+c0+j] = tanhf(sTs[r*256+c0+j] + s);
                    }
                }
            }
            __syncthreads();
        }

        // logits = soa @ Wsym + bsym + mask; pipelined; argmax
        {
            unsigned long long best[RPB] = {0ull,0ull,0ull,0ull};
            if (tid < 500) {
                int c0 = tid*4;
                ull a01[4] = {0,0,0,0}, a23[4] = {0,0,0,0};
                float4 wA[8], wB[8];
                #pragma unroll
                for (int u=0;u<8;u++) wA[u] = *(const float4*)(Wsym + (size_t)u*Vv + c0);
                for (int it = 0; it < 16; ++it) {
                    int kA = it*16;
                    #pragma unroll
                    for (int u=0;u<8;u++) wB[u] = *(const float4*)(Wsym + (size_t)(kA+8+u)*Vv + c0);
                    #pragma unroll
                    for (int u=0;u<8;u++) {
                        ull x01 = *(const ull*)(sSoaP + (kA+u)*4);
                        ull x23 = *(const ull*)(sSoaP + (kA+u)*4 + 2);
                        ull p0 = pk2(wA[u].x,wA[u].x), p1 = pk2(wA[u].y,wA[u].y);
                        ull p2 = pk2(wA[u].z,wA[u].z), p3 = pk2(wA[u].w,wA[u].w);
                        FMA2(a01[0],x01,p0); FMA2(a23[0],x23,p0);
                        FMA2(a01[1],x01,p1); FMA2(a23[1],x23,p1);
                        FMA2(a01[2],x01,p2); FMA2(a23[2],x23,p2);
                        FMA2(a01[3],x01,p3); FMA2(a23[3],x23,p3);
                    }
                    int kAn = (it < 15) ? kA + 16 : 0;
                    #pragma unroll
                    for (int u=0;u<8;u++) wA[u] = *(const float4*)(Wsym + (size_t)(kAn+u)*Vv + c0);
                    #pragma unroll
                    for (int u=0;u<8;u++) {
                        ull x01 = *(const ull*)(sSoaP + (kA+8+u)*4);
                        ull x23 = *(const ull*)(sSoaP + (kA+8+u)*4 + 2);
                        ull p0 = pk2(wB[u].x,wB[u].x), p1 = pk2(wB[u].y,wB[u].y);
                        ull p2 = pk2(wB[u].z,wB[u].z), p3 = pk2(wB[u].w,wB[u].w);
                        FMA2(a01[0],x01,p0); FMA2(a23[0],x23,p0);
                        FMA2(a01[1],x01,p1); FMA2(a23[1],x23,p1);
                        FMA2(a01[2],x01,p2); FMA2(a23[2],x23,p2);
                        FMA2(a01[3],x01,p3); FMA2(a23[3],x23,p3);
                    }
                }
                float4 bs = *(const float4*)(bsym + c0);
                float vb[4] = {bs.x, bs.y, bs.z, bs.w};
                float vr[RPB][4];
                #pragma unroll
                for (int j=0;j<4;j++) {
                    float2 p01 = up2(a01[j]), p23 = up2(a23[j]);
                    vr[0][j] = p01.x + vb[j];
                    vr[1][j] = p01.y + vb[j];
                    vr[2][j] = p23.x + vb[j];
                    vr[3][j] = p23.y + vb[j];
                }
                #pragma unroll
                for (int r=0;r<RPB;r++) {
                    int row = t*Bb + b0 + r;
                    uchar4 wm = *(const uchar4*)(d_w + (size_t)row*Vv + c0);
                    unsigned char wmv[4] = {wm.x, wm.y, wm.z, wm.w};
                    float4 st;
                    float* stp = &st.x;
                    #pragma unroll
                    for (int j=0;j<4;j++) {
                        float v = vr[r][j];
                        if (!wmv[j]) v += LT;
                        stp[j] = v;
                        unsigned long long key = ((unsigned long long)f2mono(v) << 32)
                                               | (0xFFFFFFFFu - (unsigned)(c0 + j));
                        if (key > best[r]) best[r] = key;
                    }
                    *(float4*)(d_clog + (size_t)row*Vv + c0) = st;
                }
            }
            #pragma unroll
            for (int r=0;r<RPB;r++) {
                unsigned long long bv = best[r];
                #pragma unroll
                for (int o=16;o;o>>=1) {
                    unsigned long long x = __shfl_xor_sync(0xffffffffu, bv, o);
                    if (x > bv) bv = x;
                }
                if (lane == 0 && bv) atomicMax(&sArg[r], bv);
            }
        }
        __syncthreads();
        if (tid < RPB) {
            sPrev[tid] = (int)(0xFFFFFFFFu - (unsigned)(sArg[tid] & 0xFFFFFFFFull));
            sArg[tid] = 0ull;
        }
        __syncthreads();
    }

    for (int i = tid; i < RPB*Dd; i += THR)
        d_ts[b0*Dd + i] = sTs[i];
}

// ============================================================================
// k_tail: per-batch lse + opts + topo + prepA. grid=256.
// ============================================================================
__global__ __launch_bounds__(256) void k_tail(const int* __restrict__ gg,
                                              const float* __restrict__ emb,
                                              float* __restrict__ out)
{
    const int b = blockIdx.x;
    const int tid = threadIdx.x;
    const int lane = tid & 31, warp = tid >> 5;
    __shared__ float sLse[SEQs];
    __shared__ float sVals[OPTo*SEQs];
    __shared__ float sSol[OPTo];
    __shared__ int   sBest;
    __shared__ int   sSym[SEQs];

    for (int t = warp; t < SEQs; t += 8) {
        const float* row = d_clog + ((size_t)t*Bb + b)*Vv;
        float m = -1e30f;
        for (int v = lane; v < Vv; v += 32) m = fmaxf(m, row[v]);
        #pragma unroll
        for (int o=16;o;o>>=1) m = fmaxf(m, __shfl_xor_sync(0xffffffffu, m, o));
        float s = 0.f;
        for (int v = lane; v < Vv; v += 32) s += expf(row[v]-m);
        #pragma unroll
        for (int o=16;o;o>>=1) s += __shfl_xor_sync(0xffffffffu, s, o);
        if (lane == 0) sLse[t] = m + logf(s);
    }
    __syncthreads();
    if (tid < OPTo*SEQs) {
        int o = tid / SEQs, t = tid % SEQs;
        int base = ((b*OPTo + o)*4)*SEQs + t;
        int m = gg[base + 3*SEQs];
        float v = 0.f;
        if (m) {
            int sym = gg[base];
            v = logf(expf(d_clog[((size_t)t*Bb + b)*Vv + sym] - sLse[t]) + 1e-13f);
        }
        sVals[tid] = v;
    }
    __syncthreads();
    if (tid < OPTo) {
        float s = 0.f;
        #pragma unroll
        for (int t=0;t<SEQs;t++) s += sVals[tid*SEQs + t];
        sSol[tid] = s;
        out[OFF_OPT + b*OPTo + tid] = s;
    }
    __syncthreads();
    if (tid == 0) {
        int bi = 0; float bv = sSol[0];
        for (int o=1;o<OPTo;o++) if (sSol[o] > bv) { bv = sSol[o]; bi = o; }
        sBest = bi;
    }
    __syncthreads();
    if (tid < 4*SEQs) {
        int c = tid / SEQs, s = tid % SEQs;
        int val = gg[((b*OPTo + sBest)*4 + c)*SEQs + s];
        out[OFF_TOPO + c*(Bb*SEQs) + b*SEQs + s] = (float)val;
        if (c == 0) { sSym[s] = val; d_sym[b*SEQs + s] = val; }
    }
    __syncthreads();
    for (int i = tid; i < SEQs*512; i += 256) {
        int s = i >> 9, k = i & 511;
        float v = (k < Dd) ? emb[(size_t)sSym[s]*Dd + k] : d_ts[b*Dd + (k - Dd)];
        d_Ahi[((size_t)b*SEQs + s)*512 + k] = __float2bfloat16(v);
    }
}

// ---------------- exact_logit GEMM: single bf16 mma, 128x128x32, double-buffered --
#define MMA16816(d, a, b) asm volatile( \
    "mma.sync.aligned.m16n8k16.row.col.f32.bf16.bf16.f32 " \
    "{%0,%1,%2,%3}, {%4,%5,%6,%7}, {%8,%9}, {%0,%1,%2,%3};\n" \
    : "+f"(d[0]), "+f"(d[1]), "+f"(d[2]), "+f"(d[3]) \
    : "r"(a[0]), "r"(a[1]), "r"(a[2]), "r"(a[3]), "r"(b[0]), "r"(b[1]))

#define XSTR 40

__global__ __launch_bounds__(256) void k_exact(const float* __restrict__ btok,
                                               const float* __restrict__ tok,
                                               float* __restrict__ out) {
    __shared__ __nv_bfloat16 sA[2][128*XSTR], sB[2][128*XSTR];
    int tid = threadIdx.x;
    int m0 = blockIdx.y*128, n0 = blockIdx.x*128;
    int lane = tid & 31, warp = tid >> 5;
    int wm = warp >> 2, wn = warp & 3;
    int g = lane >> 2, tq = lane & 3;
    float acc[4][4][4];
    #pragma unroll
    for (int i=0;i<4;i++) {
        #pragma unroll
        for (int j=0;j<4;j++) {
            #pragma unroll
            for (int q=0;q<4;q++) acc[i][j][q] = 0.f;
        }
    }

    int row = tid >> 1;
    int kh  = (tid & 1) << 4;
    int nr  = n0 + row;
    const bool nok = (nr < VTt);

    uint4 ra0, ra1, rb0, rb1;
    const uint4 z0 = make_uint4(0,0,0,0);

    {
        const uint4* p = (const uint4*)(d_Ahi + (size_t)(m0+row)*512 + kh);
        ra0 = p[0]; ra1 = p[1];
        rb0 = z0; rb1 = z0;
        if (nok) {
            const uint4* q = (const uint4*)(d_WhiT + (size_t)nr*512 + kh);
            rb0 = q[0]; rb1 = q[1];
        }
    }
    *(uint4*)&sA[0][row*XSTR + kh]     = ra0;
    *(uint4*)&sA[0][row*XSTR + kh + 8] = ra1;
    *(uint4*)&sB[0][row*XSTR + kh]     = rb0;
    *(uint4*)&sB[0][row*XSTR + kh + 8] = rb1;
    __syncthreads();

    int buf = 0;
    for (int k0 = 0; k0 < 512; k0 += 32) {
        int nxt = k0 + 32;
        if (nxt < 512) {
            const uint4* p = (const uint4*)(d_Ahi + (size_t)(m0+row)*512 + nxt + kh);
            ra0 = p[0]; ra1 = p[1];
            rb0 = z0; rb1 = z0;
            if (nok) {
                const uint4* q = (const uint4*)(d_WhiT + (size_t)nr*512 + nxt + kh);
                rb0 = q[0]; rb1 = q[1];
            }
        }
        const __nv_bfloat16* cA = sA[buf];
        const __nv_bfloat16* cB = sB[buf];
        #pragma unroll
        for (int ks = 0; ks < 2; ks++) {
            int kb = ks*16;
            uint32_t ah[4][4];
            #pragma unroll
            for (int mi=0;mi<4;mi++) {
                int rb = wm*64 + mi*16;
                int c0 = kb + tq*2;
                ah[mi][0] = *(const uint32_t*)&cA[(rb+g)*XSTR + c0];
                ah[mi][1] = *(const uint32_t*)&cA[(rb+g+8)*XSTR + c0];
                ah[mi][2] = *(const uint32_t*)&cA[(rb+g)*XSTR + c0 + 8];
                ah[mi][3] = *(const uint32_t*)&cA[(rb+g+8)*XSTR + c0 + 8];
            }
            uint32_t bh[4][2];
            #pragma unroll
            for (int ni=0;ni<4;ni++) {
                int nb = wn*32 + ni*8 + g;
                bh[ni][0] = *(const uint32_t*)&cB[nb*XSTR + kb + tq*2];
                bh[ni][1] = *(const uint32_t*)&cB[nb*XSTR + kb + tq*2 + 8];
            }
            #pragma unroll
            for (int mi=0;mi<4;mi++) {
                #pragma unroll
                for (int ni=0;ni<4;ni++) {
                    MMA16816(acc[mi][ni], ah[mi], bh[ni]);
                }
            }
        }
        if (nxt < 512) {
            *(uint4*)&sA[buf^1][row*XSTR + kh]     = ra0;
            *(uint4*)&sA[buf^1][row*XSTR + kh + 8] = ra1;
            *(uint4*)&sB[buf^1][row*XSTR + kh]     = rb0;
            *(uint4*)&sB[buf^1][row*XSTR + kh + 8] = rb1;
            __syncthreads();
            buf ^= 1;
        }
    }

    const float LT = logf(1e-13f);
    #pragma unroll
    for (int mi=0;mi<4;mi++) {
        int r0 = m0 + wm*64 + mi*16 + g;
        int s0 = d_sym[r0];
        int s1 = d_sym[r0 + 8];
        #pragma unroll
        for (int ni=0;ni<4;ni++) {
            int c0 = n0 + wn*32 + ni*8 + tq*2;
            if (c0 < VTt) {
                float b0 = btok[c0];
                out[OFF_EX + (size_t)r0*VTt + c0]     = acc[mi][ni][0] + b0 + (tok[(size_t)s0*VTt + c0] > 0.f ? 0.f : LT);
                out[OFF_EX + (size_t)(r0+8)*VTt + c0] = acc[mi][ni][2] + b0 + (tok[(size_t)s1*VTt + c0] > 0.f ? 0.f : LT);
            }
            if (c0 + 1 < VTt) {
                float b1 = btok[c0+1];
                out[OFF_EX + (size_t)r0*VTt + c0+1]     = acc[mi][ni][1] + b1 + (tok[(size_t)s0*VTt + c0+1] > 0.f ? 0.f : LT);
                out[OFF_EX + (size_t)(r0+8)*VTt + c0+1] = acc[mi][ni][3] + b1 + (tok[(size_t)s1*VTt + c0+1] > 0.f ? 0.f : LT);
            }
        }
    }
}

// ---------------- host launcher ----------------
extern "C" void kernel_launch(void* const* d_in, const int* in_sizes, int n_in,
                              void* d_out, int out_size) {
    const int*   lhs   = (const int*)d_in[0];
    const int*   lmask = (const int*)d_in[1];
    const float* ts0   = (const float*)d_in[2];
    const int*   gg    = (const int*)d_in[3];
    const float* emb   = (const float*)d_in[4];
    const float* mem   = (const float*)d_in[5];
    const float* Wx    = (const float*)d_in[6];
    const float* Wh    = (const float*)d_in[7];
    const float* bx    = (const float*)d_in[8];
    const float* bh    = (const float*)d_in[9];
    const float* Wc    = (const float*)d_in[10];
    const float* bc    = (const float*)d_in[11];
    const float* Wsym  = (const float*)d_in[12];
    const float* bsym  = (const float*)d_in[13];
    const float* Wtok  = (const float*)d_in[14];
    const float* btok  = (const float*)d_in[15];
    const float* tok   = (const float*)d_in[16];
    float* out = (float*)d_out;

    static bool attr_set = false;
    if (!attr_set) {
        cudaFuncSetAttribute(k_steps, cudaFuncAttributeMaxDynamicSharedMemorySize, SM_BYTES);
        attr_set = true;
    }

    k_w<<<SEQs*Bb, 64>>>(gg);
    k_prepW<<<5008, 256>>>(Wtok);
    k_copy<<<642, 256>>>(lhs, lmask, gg, out);
    k_steps<<<GSTEP, THR, SM_BYTES>>>(lhs, ts0, emb, mem, Wx, bx, Wh, bh, Wc, bc, Wsym, bsym);
    k_tail<<<Bb, 256>>>(gg, emb, out);
    k_exact<<<dim3((VTt+127)/128, (Bb*SEQs)/128), 256>>>(btok, tok, out);
}